// round 12
// baseline (speedup 1.0000x reference)
#include <cuda_runtime.h>
#include <cuda_fp16.h>
#include <cstdint>

// Shape: B=2, H=16, S=2048, D=128, fp32 in/out. GPT-Neo attention, no 1/sqrt(d).
constexpr int Sc = 2048, Dc = 128, NTH = 128;
constexpr int ROWE = 136;                   // half elems per padded smem row
constexpr int BHSD = 2 * 16 * 2048 * 128;   // 8388608
constexpr float L2E = 1.4426950408889634f;  // log2(e)

// Preconverted fp16 copies (device scratch; no runtime alloc).
// Q is pre-scaled by log2(e): softmax runs in exp2 domain.
__device__ __align__(16) __half g_qhi[BHSD];
__device__ __align__(16) __half g_qlo[BHSD];
__device__ __align__(16) __half g_khi[BHSD];
__device__ __align__(16) __half g_klo[BHSD];
__device__ __align__(16) __half g_vh [BHSD];

// ---- smem per CTA: 2-slot KV ring (Q staged transiently into slot 0) ----
constexpr int TILEK_B = 64 * ROWE * 2;      // 17408 (one 64-row fp16 tile)
constexpr int SLOT_B  = 3 * TILEK_B;        // KHI, KLO, VH = 52224
constexpr int SMEM_BYTES = 2 * SLOT_B;      // 104448 -> 2 CTAs/SM

__device__ __forceinline__ uint32_t smem_u32(const void* p) {
    uint32_t a;
    asm("{ .reg .u64 t; cvta.to.shared.u64 t, %1; cvt.u32.u64 %0, t; }"
        : "=r"(a) : "l"(p));
    return a;
}
__device__ __forceinline__ void cpa(uint32_t d, const void* s) {
    asm volatile("cp.async.cg.shared.global [%0], [%1], 16;" :: "r"(d), "l"(s));
}
#define CP_COMMIT()  asm volatile("cp.async.commit_group;" ::: "memory")
#define CP_WAIT1()   asm volatile("cp.async.wait_group 1;" ::: "memory")
#define CP_WAITALL() asm volatile("cp.async.wait_group 0;" ::: "memory")

__device__ __forceinline__ void ldsm4(uint32_t* r, uint32_t a) {
    asm volatile("ldmatrix.sync.aligned.m8n8.x4.shared.b16 {%0,%1,%2,%3}, [%4];"
                 : "=r"(r[0]), "=r"(r[1]), "=r"(r[2]), "=r"(r[3]) : "r"(a));
}
__device__ __forceinline__ void ldsm4t(uint32_t* r, uint32_t a) {
    asm volatile("ldmatrix.sync.aligned.m8n8.x4.trans.shared.b16 {%0,%1,%2,%3}, [%4];"
                 : "=r"(r[0]), "=r"(r[1]), "=r"(r[2]), "=r"(r[3]) : "r"(a));
}
__device__ __forceinline__ void mma16816(float* d, const uint32_t* a, const uint32_t* b) {
    asm volatile("mma.sync.aligned.m16n8k16.row.col.f32.f16.f16.f32 "
                 "{%0,%1,%2,%3}, {%4,%5,%6,%7}, {%8,%9}, {%0,%1,%2,%3};"
                 : "+f"(d[0]), "+f"(d[1]), "+f"(d[2]), "+f"(d[3])
                 : "r"(a[0]), "r"(a[1]), "r"(a[2]), "r"(a[3]), "r"(b[0]), "r"(b[1]));
}
__device__ __forceinline__ uint32_t packh(__half a, __half b) {
    __half2 v(a, b);
    return *(uint32_t*)&v;
}
__device__ __forceinline__ uint32_t pack2(float a, float b) {
    __half2 v = __floats2half2_rn(a, b);
    return *(uint32_t*)&v;
}
__device__ __forceinline__ float ex2(float x) {
    float y;
    asm("ex2.approx.f32 %0, %1;" : "=f"(y) : "f"(x));
    return y;
}

// ---- preconvert: Q*log2e -> fp16 hi/lo; K -> fp16 hi/lo; V -> fp16 ----
__global__ __launch_bounds__(256)
void convert_split(const float* __restrict__ Q, const float* __restrict__ K,
                   const float* __restrict__ V)
{
    int i = (blockIdx.x * 256 + threadIdx.x) * 4;
    if (blockIdx.y == 2) {
        float4 x = *(const float4*)(V + i);
        *(uint2*)&g_vh[i] = make_uint2(pack2(x.x, x.y), pack2(x.z, x.w));
        return;
    }
    const float* src = (blockIdx.y == 0) ? Q : K;
    __half* hi = (blockIdx.y == 0) ? g_qhi : g_khi;
    __half* lo = (blockIdx.y == 0) ? g_qlo : g_klo;
    const float sc = (blockIdx.y == 0) ? L2E : 1.0f;
    float4 x = *(const float4*)(src + i);
    x.x *= sc; x.y *= sc; x.z *= sc; x.w *= sc;
    __half h0 = __float2half(x.x), h1 = __float2half(x.y);
    __half h2 = __float2half(x.z), h3 = __float2half(x.w);
    *(uint2*)&hi[i] = make_uint2(packh(h0, h1), packh(h2, h3));
    *(uint2*)&lo[i] = make_uint2(
        pack2(x.x - __half2float(h0), x.y - __half2float(h1)),
        pack2(x.z - __half2float(h2), x.w - __half2float(h3)));
}

// stage one 64-row KV group (K hi/lo + V) via cp.async, 128 threads
__device__ __forceinline__ void stage_kv(uint32_t dst, int bh, int kv0, int tid) {
    const char* gkh = (const char*)(g_khi + ((size_t)bh * Sc + kv0) * Dc);
    const char* gkl = (const char*)(g_klo + ((size_t)bh * Sc + kv0) * Dc);
    const char* gvh = (const char*)(g_vh  + ((size_t)bh * Sc + kv0) * Dc);
    #pragma unroll
    for (int i2 = 0; i2 < 8; i2++) {
        int id = tid + 128 * i2;               // 0..1023
        int r = id >> 4, c = id & 15;
        uint32_t so = (uint32_t)(r * (ROWE * 2) + c * 16);
        uint32_t go = (uint32_t)(r * 256 + c * 16);
        cpa(dst + so, gkh + go);
        cpa(dst + TILEK_B + so, gkl + go);
        cpa(dst + 2 * TILEK_B + so, gvh + go);
    }
}

__global__ __launch_bounds__(NTH, 2)
void attn_hmma(const float* __restrict__ AM, const float* __restrict__ HM,
               const float* __restrict__ CTX, float* __restrict__ O)
{
    extern __shared__ char sm[];
    const uint32_t sb = smem_u32(sm);

    const int tid = threadIdx.x, lane = tid & 31, warp = tid >> 5;   // 4 warps
    const int wrow = warp * 16;                    // row base within 64-row tile
    const int bx = blockIdx.x;
    const int qsub = (Sc / 64 - 1) - (bx >> 5);    // LPT: heavy tiles first
    const int bh = bx & 31, b = bh >> 4, h = bh & 15;
    const int q0 = qsub * 64;                      // CTA's first global q row
    const int NS = qsub + 1;                       // 64-col kv steps

    // ldmatrix lane->address offsets (bytes)
    const uint32_t aoffA = (uint32_t)((wrow + (lane & 15)) * ROWE + (lane >> 4) * 8) * 2;
    const uint32_t aoffB = (uint32_t)(((lane & 7) + ((lane >> 4) << 3)) * ROWE
                                      + (((lane >> 3) & 1) << 3)) * 2;
    const uint32_t aoffBT = (uint32_t)(((lane & 7) + (((lane >> 3) & 1) << 3)) * ROWE
                                       + ((lane >> 4) << 3)) * 2;

    float o[64];
    #pragma unroll
    for (int i = 0; i < 64; i++) o[i] = 0.f;
    float m0 = -1e30f, m1 = -1e30f, l0 = 0.f, l1 = 0.f;

    // ---- prologue: stage this CTA's 64 Q rows into slot 0, pull to regs ----
    {
        const char* gqh = (const char*)(g_qhi + ((size_t)bh * Sc + q0) * Dc);
        const char* gql = (const char*)(g_qlo + ((size_t)bh * Sc + q0) * Dc);
        #pragma unroll
        for (int i2 = 0; i2 < 8; i2++) {
            int id = tid + 128 * i2;               // 0..1023
            int r = id >> 4, c = id & 15;
            uint32_t so = (uint32_t)(r * (ROWE * 2) + c * 16);
            uint32_t go = (uint32_t)(r * 256 + c * 16);
            cpa(sb + so, gqh + go);                // Q hi at slot0 base
            cpa(sb + TILEK_B + so, gql + go);      // Q lo right after
        }
    }
    CP_COMMIT();
    CP_WAITALL();
    __syncthreads();
    uint32_t qfh[32], qfl[32];
    #pragma unroll
    for (int ks = 0; ks < 8; ks++) {
        ldsm4(&qfh[ks * 4], sb + aoffA + ks * 32);
        ldsm4(&qfl[ks * 4], sb + TILEK_B + aoffA + ks * 32);
    }
    __syncthreads();       // all warps hold Q in regs -> slot 0 reusable
    stage_kv(sb, bh, 0, tid);          // KV0 -> slot 0
    CP_COMMIT();

    const float2* AMp = (const float2*)(AM + (size_t)b * Sc);
    const float2* CXp = (const float2*)(CTX + (size_t)b * Sc);

    for (int js = 0; js < NS; js++) {
        const int kv0 = js * 64;
        __syncthreads();   // all warps past js-1 -> slot (js+1)&1 free
        if (js + 1 < NS) {
            stage_kv(sb + (uint32_t)((js + 1) & 1) * SLOT_B, bh, kv0 + 64, tid);
            CP_COMMIT();
            CP_WAIT1();    // KV_js landed (KV_{js+1} in flight)
        } else {
            CP_WAITALL();
        }
        __syncthreads();   // KV_js visible to all warps

        const uint32_t bKHI = sb + (uint32_t)(js & 1) * SLOT_B;
        const uint32_t bKLO = bKHI + TILEK_B;
        const uint32_t bVH  = bKHI + 2 * TILEK_B;

        // ===== S = Q K^T (3 fp16 split passes, np-paired; log2 domain) =====
        float s[32];
        #pragma unroll
        for (int i = 0; i < 32; i++) s[i] = 0.f;

        #pragma unroll
        for (int ks = 0; ks < 8; ks++) {
            const uint32_t* ah = &qfh[ks * 4];
            const uint32_t* al = &qfl[ks * 4];
            #pragma unroll
            for (int pp = 0; pp < 2; pp++) {
                uint32_t b0h[4], b0l[4], b1h[4], b1l[4];
                uint32_t bo0 = aoffB + (uint32_t)((2 * pp) * 16 * ROWE) * 2 + ks * 32;
                uint32_t bo1 = bo0 + (uint32_t)(16 * ROWE) * 2;
                ldsm4(b0h, bKHI + bo0);
                ldsm4(b1h, bKHI + bo1);
                ldsm4(b0l, bKLO + bo0);
                ldsm4(b1l, bKLO + bo1);
                float* s0 = &s[(4 * pp) * 4];
                float* s1 = &s[(4 * pp + 1) * 4];
                float* s2 = &s[(4 * pp + 2) * 4];
                float* s3 = &s[(4 * pp + 3) * 4];
                mma16816(s0, ah, b0h);  mma16816(s1, ah, b0h + 2);
                mma16816(s2, ah, b1h);  mma16816(s3, ah, b1h + 2);
                mma16816(s0, ah, b0l);  mma16816(s1, ah, b0l + 2);
                mma16816(s2, ah, b1l);  mma16816(s3, ah, b1l + 2);
                mma16816(s0, al, b0h);  mma16816(s1, al, b0h + 2);
                mma16816(s2, al, b1h);  mma16816(s3, al, b1h + 2);
            }
        }

        // ===== mask (AM scaled into log2 domain via FFMA) + row max =====
        #pragma unroll
        for (int t = 0; t < 8; t++) {
            float2 a2 = __ldg(&AMp[kv0 / 2 + t * 4 + (lane & 3)]);
            s[t * 4 + 0] = fmaf(a2.x, L2E, s[t * 4 + 0]);
            s[t * 4 + 1] = fmaf(a2.y, L2E, s[t * 4 + 1]);
            s[t * 4 + 2] = fmaf(a2.x, L2E, s[t * 4 + 2]);
            s[t * 4 + 3] = fmaf(a2.y, L2E, s[t * 4 + 3]);
        }
        if (js == NS - 1) {        // diagonal 64x64 tile
            const int wr0 = wrow + (lane >> 2), wr1 = wr0 + 8;  // local rows
            #pragma unroll
            for (int t = 0; t < 8; t++) {
                int c0 = t * 8 + (lane & 3) * 2;                // local col
                if (c0     > wr0) s[t * 4 + 0] = -1e30f;
                if (c0 + 1 > wr0) s[t * 4 + 1] = -1e30f;
                if (c0     > wr1) s[t * 4 + 2] = -1e30f;
                if (c0 + 1 > wr1) s[t * 4 + 3] = -1e30f;
            }
        }
        float mx0 = -1e30f, mx1 = -1e30f;
        #pragma unroll
        for (int t = 0; t < 8; t++) {
            mx0 = fmaxf(mx0, fmaxf(s[t * 4 + 0], s[t * 4 + 1]));
            mx1 = fmaxf(mx1, fmaxf(s[t * 4 + 2], s[t * 4 + 3]));
        }
        mx0 = fmaxf(mx0, __shfl_xor_sync(0xffffffffu, mx0, 1));
        mx0 = fmaxf(mx0, __shfl_xor_sync(0xffffffffu, mx0, 2));
        mx1 = fmaxf(mx1, __shfl_xor_sync(0xffffffffu, mx1, 1));
        mx1 = fmaxf(mx1, __shfl_xor_sync(0xffffffffu, mx1, 2));
        const float mn0 = fmaxf(m0, mx0), mn1 = fmaxf(m1, mx1);
        const float corr0 = ex2(m0 - mn0), corr1 = ex2(m1 - mn1);
        m0 = mn0;  m1 = mn1;

        #pragma unroll
        for (int t = 0; t < 16; t++) {
            o[t * 4 + 0] *= corr0; o[t * 4 + 1] *= corr0;
            o[t * 4 + 2] *= corr1; o[t * 4 + 3] *= corr1;
        }
        l0 *= corr0;  l1 *= corr1;

        // ===== exp2 + pack all 64 cols, then PV =====
        uint32_t ph0[8], ph1[8];
        float ls0 = 0.f, ls1 = 0.f;
        #pragma unroll
        for (int t = 0; t < 8; t++) {
            float p0 = ex2(s[t * 4 + 0] - mn0);
            float p1 = ex2(s[t * 4 + 1] - mn0);
            float p2 = ex2(s[t * 4 + 2] - mn1);
            float p3 = ex2(s[t * 4 + 3] - mn1);
            ls0 += p0 + p1;  ls1 += p2 + p3;
            float2 cx = __ldg(&CXp[kv0 / 2 + t * 4 + (lane & 3)]);
            ph0[t] = pack2(p0 * cx.x, p1 * cx.y);
            ph1[t] = pack2(p2 * cx.x, p3 * cx.y);
        }
        ls0 += __shfl_xor_sync(0xffffffffu, ls0, 1);
        ls0 += __shfl_xor_sync(0xffffffffu, ls0, 2);
        ls1 += __shfl_xor_sync(0xffffffffu, ls1, 1);
        ls1 += __shfl_xor_sync(0xffffffffu, ls1, 2);
        l0 += ls0;  l1 += ls1;

        #pragma unroll
        for (int ks = 0; ks < 4; ks++) {
            uint32_t af[4] = {ph0[2 * ks], ph1[2 * ks],
                              ph0[2 * ks + 1], ph1[2 * ks + 1]};
            #pragma unroll
            for (int dp = 0; dp < 8; dp++) {
                uint32_t bv[4];
                uint32_t bo = aoffBT + (uint32_t)(ks * 16 * ROWE) * 2 + dp * 32;
                ldsm4t(bv, bVH + bo);
                mma16816(&o[(2 * dp) * 4],     af, bv);
                mma16816(&o[(2 * dp + 1) * 4], af, bv + 2);
            }
        }
    }

    // ================= epilogue =================
    const float hm = __ldg(&HM[h]);
    const float sc0 = hm / l0, sc1 = hm / l1;
    const int gr0 = q0 + wrow + (lane >> 2);
    float* O0 = O + ((size_t)bh * Sc + gr0) * Dc;
    float* O1 = O0 + 8 * Dc;
    #pragma unroll
    for (int t = 0; t < 16; t++) {
        int c0 = t * 8 + (lane & 3) * 2;
        *(float2*)&O0[c0] = make_float2(o[t * 4 + 0] * sc0, o[t * 4 + 1] * sc0);
        *(float2*)&O1[c0] = make_float2(o[t * 4 + 2] * sc1, o[t * 4 + 3] * sc1);
    }
}

extern "C" void kernel_launch(void* const* d_in, const int* in_sizes, int n_in,
                              void* d_out, int out_size)
{
    const float* q   = (const float*)d_in[0];
    const float* k   = (const float*)d_in[1];
    const float* v   = (const float*)d_in[2];
    const float* am  = (const float*)d_in[3];
    const float* hm  = (const float*)d_in[4];
    const float* ctx = (const float*)d_in[5];
    float* out = (float*)d_out;

    convert_split<<<dim3(BHSD / (256 * 4), 3), 256>>>(q, k, v);

    cudaFuncSetAttribute(attn_hmma, cudaFuncAttributeMaxDynamicSharedMemorySize,
                         SMEM_BYTES);
    attn_hmma<<<1024, NTH, SMEM_BYTES>>>(am, hm, ctx, out);
}

// round 13
// speedup vs baseline: 1.0430x; 1.0430x over previous
#include <cuda_runtime.h>
#include <cuda_fp16.h>
#include <cstdint>

// Shape: B=2, H=16, S=2048, D=128, fp32 in/out. GPT-Neo attention, no 1/sqrt(d).
constexpr int Sc = 2048, Dc = 128, NTH = 256;
constexpr int ROWE = 136;                   // half elems per padded smem row
constexpr int BHSD = 2 * 16 * 2048 * 128;   // 8388608
constexpr float L2E = 1.4426950408889634f;  // log2(e)

// Preconverted fp16 copies of K (hi/lo) and V (device scratch; no runtime alloc).
__device__ __align__(16) __half g_khi[BHSD];
__device__ __align__(16) __half g_klo[BHSD];
__device__ __align__(16) __half g_vh [BHSD];

// ---- smem: 4-slot KV ring ----
constexpr int TILEK_B = 64 * ROWE * 2;      // 17408
constexpr int SLOT_B  = 3 * TILEK_B;        // KHI, KLO, VH = 52224
constexpr int SMEM_BYTES = 4 * SLOT_B;      // 208896 (<= 227KB)

__device__ __forceinline__ uint32_t smem_u32(const void* p) {
    uint32_t a;
    asm("{ .reg .u64 t; cvta.to.shared.u64 t, %1; cvt.u32.u64 %0, t; }"
        : "=r"(a) : "l"(p));
    return a;
}
__device__ __forceinline__ void cpa(uint32_t d, const void* s) {
    asm volatile("cp.async.cg.shared.global [%0], [%1], 16;" :: "r"(d), "l"(s));
}
#define CP_COMMIT()  asm volatile("cp.async.commit_group;" ::: "memory")
#define CP_WAITALL() asm volatile("cp.async.wait_group 0;" ::: "memory")

__device__ __forceinline__ void ldsm4(uint32_t* r, uint32_t a) {
    asm volatile("ldmatrix.sync.aligned.m8n8.x4.shared.b16 {%0,%1,%2,%3}, [%4];"
                 : "=r"(r[0]), "=r"(r[1]), "=r"(r[2]), "=r"(r[3]) : "r"(a));
}
__device__ __forceinline__ void ldsm4t(uint32_t* r, uint32_t a) {
    asm volatile("ldmatrix.sync.aligned.m8n8.x4.trans.shared.b16 {%0,%1,%2,%3}, [%4];"
                 : "=r"(r[0]), "=r"(r[1]), "=r"(r[2]), "=r"(r[3]) : "r"(a));
}
__device__ __forceinline__ void mma16816(float* d, const uint32_t* a, const uint32_t* b) {
    asm volatile("mma.sync.aligned.m16n8k16.row.col.f32.f16.f16.f32 "
                 "{%0,%1,%2,%3}, {%4,%5,%6,%7}, {%8,%9}, {%0,%1,%2,%3};"
                 : "+f"(d[0]), "+f"(d[1]), "+f"(d[2]), "+f"(d[3])
                 : "r"(a[0]), "r"(a[1]), "r"(a[2]), "r"(a[3]), "r"(b[0]), "r"(b[1]));
}
__device__ __forceinline__ uint32_t packh(__half a, __half b) {
    __half2 v(a, b);
    return *(uint32_t*)&v;
}
__device__ __forceinline__ uint32_t pack2(float a, float b) {
    __half2 v = __floats2half2_rn(a, b);
    return *(uint32_t*)&v;
}
__device__ __forceinline__ float ex2(float x) {
    float y;
    asm("ex2.approx.f32 %0, %1;" : "=f"(y) : "f"(x));
    return y;
}
// scale by log2(e), split to fp16 hi + residual lo, pack
__device__ __forceinline__ void splitpack(float2 v, uint32_t& hi, uint32_t& lo) {
    v.x *= L2E;  v.y *= L2E;
    __half hx = __float2half(v.x), hy = __float2half(v.y);
    hi = packh(hx, hy);
    lo = pack2(v.x - __half2float(hx), v.y - __half2float(hy));
}

// ---- preconvert: K -> fp16 hi/lo; V -> fp16. Pure BW. ----
__global__ __launch_bounds__(256)
void convert_split(const float* __restrict__ K, const float* __restrict__ V)
{
    int i = (blockIdx.x * 256 + threadIdx.x) * 4;
    if (blockIdx.y == 1) {
        float4 x = *(const float4*)(V + i);
        *(uint2*)&g_vh[i] = make_uint2(pack2(x.x, x.y), pack2(x.z, x.w));
        return;
    }
    float4 x = *(const float4*)(K + i);
    __half h0 = __float2half(x.x), h1 = __float2half(x.y);
    __half h2 = __float2half(x.z), h3 = __float2half(x.w);
    *(uint2*)&g_khi[i] = make_uint2(packh(h0, h1), packh(h2, h3));
    *(uint2*)&g_klo[i] = make_uint2(
        pack2(x.x - __half2float(h0), x.y - __half2float(h1)),
        pack2(x.z - __half2float(h2), x.w - __half2float(h3)));
}

// stage one 64-row KV group (K hi/lo + V) via cp.async, 256 threads
__device__ __forceinline__ void stage_kv(uint32_t dst, int bh, int kv0, int tid) {
    const char* gkh = (const char*)(g_khi + ((size_t)bh * Sc + kv0) * Dc);
    const char* gkl = (const char*)(g_klo + ((size_t)bh * Sc + kv0) * Dc);
    const char* gvh = (const char*)(g_vh  + ((size_t)bh * Sc + kv0) * Dc);
    #pragma unroll
    for (int i2 = 0; i2 < 4; i2++) {
        int id = tid + 256 * i2;               // 0..1023
        int r = id >> 4, c = id & 15;
        uint32_t so = (uint32_t)(r * (ROWE * 2) + c * 16);
        uint32_t go = (uint32_t)(r * 256 + c * 16);
        cpa(dst + so, gkh + go);
        cpa(dst + TILEK_B + so, gkl + go);
        cpa(dst + 2 * TILEK_B + so, gvh + go);
    }
}

__global__ __launch_bounds__(NTH, 1)
void attn_hmma(const float* __restrict__ Q, const float* __restrict__ AM,
               const float* __restrict__ HM, const float* __restrict__ CTX,
               float* __restrict__ O)
{
    extern __shared__ char sm[];
    const uint32_t sb = smem_u32(sm);

    const int tid = threadIdx.x, lane = tid & 31, warp = tid >> 5;
    const int wrow = warp * 16;
    const int bx = blockIdx.x;
    const int qi = (Sc / 128 - 1) - (bx >> 5);      // LPT: heavy CTAs first
    const int bh = bx & 31, b = bh >> 4, h = bh & 15;
    const int q0 = qi * 128;
    const int NS = 2 * (qi + 1);                    // 64-col kv steps (even)

    // ldmatrix lane->address offsets (bytes)
    const uint32_t aoffB = (uint32_t)(((lane & 7) + ((lane >> 4) << 3)) * ROWE
                                      + (((lane >> 3) & 1) << 3)) * 2;
    const uint32_t aoffBT = (uint32_t)(((lane & 7) + (((lane >> 3) & 1) << 3)) * ROWE
                                       + ((lane >> 4) << 3)) * 2;

    float o[64];
    #pragma unroll
    for (int i = 0; i < 64; i++) o[i] = 0.f;
    float m0 = -1e30f, m1 = -1e30f, l0 = 0.f, l1 = 0.f;

    // ---- prologue: launch KV0/KV1 stages, then build Q fragments from fp32 ----
    stage_kv(sb, bh, 0, tid);
    CP_COMMIT();
    stage_kv(sb + SLOT_B, bh, 64, tid);
    CP_COMMIT();

    // Direct LDG of this thread's Q fragment elements (mma A-frag layout),
    // scaled by log2(e) and split hi/lo in registers. Overlaps cp.async above.
    uint32_t qfh[32], qfl[32];
    {
        const float* Qr0 = Q + ((size_t)bh * Sc + q0 + wrow + (lane >> 2)) * Dc;
        const float* Qr1 = Qr0 + 8 * Dc;
        const int c2 = (lane & 3) * 2;
        #pragma unroll
        for (int ks = 0; ks < 8; ks++) {
            float2 x0 = __ldg((const float2*)(Qr0 + ks * 16 + c2));
            float2 x1 = __ldg((const float2*)(Qr1 + ks * 16 + c2));
            float2 x2 = __ldg((const float2*)(Qr0 + ks * 16 + 8 + c2));
            float2 x3 = __ldg((const float2*)(Qr1 + ks * 16 + 8 + c2));
            splitpack(x0, qfh[ks * 4 + 0], qfl[ks * 4 + 0]);
            splitpack(x1, qfh[ks * 4 + 1], qfl[ks * 4 + 1]);
            splitpack(x2, qfh[ks * 4 + 2], qfl[ks * 4 + 2]);
            splitpack(x3, qfh[ks * 4 + 3], qfl[ks * 4 + 3]);
        }
    }

    const float2* AMp = (const float2*)(AM + (size_t)b * Sc);
    const float2* CXp = (const float2*)(CTX + (size_t)b * Sc);
    const bool lower = (warp < 4);      // sub-step traversal order per warp half

    // ==== main loop: one barrier per 2 steps; upper warps reverse sub order ====
    for (int js2 = 0; js2 < NS; js2 += 2) {
        CP_WAITALL();           // KV_{js2}, KV_{js2+1} landed
        __syncthreads();        // visible to all warps; all warps past js2-1
        if (js2 + 2 < NS) { stage_kv(sb + (uint32_t)((js2 + 2) & 3) * SLOT_B,
                                     bh, (js2 + 2) * 64, tid); CP_COMMIT(); }
        if (js2 + 3 < NS) { stage_kv(sb + (uint32_t)((js2 + 3) & 3) * SLOT_B,
                                     bh, (js2 + 3) * 64, tid); CP_COMMIT(); }

        #pragma unroll
        for (int sub = 0; sub < 2; sub++) {
            const int js = js2 + (lower ? sub : 1 - sub);
            // warps 0-3: second diagonal half-step fully masked -> P==0.
            if (js == 2 * qi + 1 && wrow < 64) continue;
            const int kv0 = js * 64;
            const uint32_t bKHI = sb + (uint32_t)(js & 3) * SLOT_B;
            const uint32_t bKLO = bKHI + TILEK_B;
            const uint32_t bVH  = bKHI + 2 * TILEK_B;

            // ===== S = Q K^T (3 fp16 split passes, np-paired; log2 domain) =====
            float s[32];
            #pragma unroll
            for (int i = 0; i < 32; i++) s[i] = 0.f;

            #pragma unroll
            for (int ks = 0; ks < 8; ks++) {
                const uint32_t* ah = &qfh[ks * 4];
                const uint32_t* al = &qfl[ks * 4];
                #pragma unroll
                for (int pp = 0; pp < 2; pp++) {
                    uint32_t b0h[4], b0l[4], b1h[4], b1l[4];
                    uint32_t bo0 = aoffB + (uint32_t)((2 * pp) * 16 * ROWE) * 2 + ks * 32;
                    uint32_t bo1 = bo0 + (uint32_t)(16 * ROWE) * 2;
                    ldsm4(b0h, bKHI + bo0);
                    ldsm4(b1h, bKHI + bo1);
                    ldsm4(b0l, bKLO + bo0);
                    ldsm4(b1l, bKLO + bo1);
                    float* s0 = &s[(4 * pp) * 4];
                    float* s1 = &s[(4 * pp + 1) * 4];
                    float* s2 = &s[(4 * pp + 2) * 4];
                    float* s3 = &s[(4 * pp + 3) * 4];
                    mma16816(s0, ah, b0h);  mma16816(s1, ah, b0h + 2);
                    mma16816(s2, ah, b1h);  mma16816(s3, ah, b1h + 2);
                    mma16816(s0, ah, b0l);  mma16816(s1, ah, b0l + 2);
                    mma16816(s2, ah, b1l);  mma16816(s3, ah, b1l + 2);
                    mma16816(s0, al, b0h);  mma16816(s1, al, b0h + 2);
                    mma16816(s2, al, b1h);  mma16816(s3, al, b1h + 2);
                }
            }

            // ===== mask (AM in log2 domain via FFMA) + tree row max =====
            #pragma unroll
            for (int t = 0; t < 8; t++) {
                float2 a2 = __ldg(&AMp[kv0 / 2 + t * 4 + (lane & 3)]);
                s[t * 4 + 0] = fmaf(a2.x, L2E, s[t * 4 + 0]);
                s[t * 4 + 1] = fmaf(a2.y, L2E, s[t * 4 + 1]);
                s[t * 4 + 2] = fmaf(a2.x, L2E, s[t * 4 + 2]);
                s[t * 4 + 3] = fmaf(a2.y, L2E, s[t * 4 + 3]);
            }
            if (js >= 2 * qi) {         // diagonal region
                const int off = kv0 - q0;
                const int wr0 = wrow + (lane >> 2), wr1 = wr0 + 8;
                #pragma unroll
                for (int t = 0; t < 8; t++) {
                    int c0 = off + t * 8 + (lane & 3) * 2;
                    if (c0     > wr0) s[t * 4 + 0] = -1e30f;
                    if (c0 + 1 > wr0) s[t * 4 + 1] = -1e30f;
                    if (c0     > wr1) s[t * 4 + 2] = -1e30f;
                    if (c0 + 1 > wr1) s[t * 4 + 3] = -1e30f;
                }
            }
            // explicit binary-tree max (depth 4 instead of 16-deep chain)
            float a0[8], a1[8];
            #pragma unroll
            for (int t = 0; t < 8; t++) {
                a0[t] = fmaxf(s[t * 4 + 0], s[t * 4 + 1]);
                a1[t] = fmaxf(s[t * 4 + 2], s[t * 4 + 3]);
            }
            #pragma unroll
            for (int w = 4; w >= 1; w >>= 1)
                #pragma unroll
                for (int t = 0; t < w; t++) {
                    a0[t] = fmaxf(a0[t], a0[t + w]);
                    a1[t] = fmaxf(a1[t], a1[t + w]);
                }
            float mx0 = a0[0], mx1 = a1[0];
            mx0 = fmaxf(mx0, __shfl_xor_sync(0xffffffffu, mx0, 1));
            mx0 = fmaxf(mx0, __shfl_xor_sync(0xffffffffu, mx0, 2));
            mx1 = fmaxf(mx1, __shfl_xor_sync(0xffffffffu, mx1, 1));
            mx1 = fmaxf(mx1, __shfl_xor_sync(0xffffffffu, mx1, 2));
            const float mn0 = fmaxf(m0, mx0), mn1 = fmaxf(m1, mx1);
            const float corr0 = ex2(m0 - mn0), corr1 = ex2(m1 - mn1);
            m0 = mn0;  m1 = mn1;

            #pragma unroll
            for (int t = 0; t < 16; t++) {
                o[t * 4 + 0] *= corr0; o[t * 4 + 1] *= corr0;
                o[t * 4 + 2] *= corr1; o[t * 4 + 3] *= corr1;
            }
            l0 *= corr0;  l1 *= corr1;

            // ===== exp2 + pack all 64 cols, then PV =====
            uint32_t ph0[8], ph1[8];
            float ls0 = 0.f, ls1 = 0.f;
            #pragma unroll
            for (int t = 0; t < 8; t++) {
                float p0 = ex2(s[t * 4 + 0] - mn0);
                float p1 = ex2(s[t * 4 + 1] - mn0);
                float p2 = ex2(s[t * 4 + 2] - mn1);
                float p3 = ex2(s[t * 4 + 3] - mn1);
                ls0 += p0 + p1;  ls1 += p2 + p3;
                float2 cx = __ldg(&CXp[kv0 / 2 + t * 4 + (lane & 3)]);
                ph0[t] = pack2(p0 * cx.x, p1 * cx.y);
                ph1[t] = pack2(p2 * cx.x, p3 * cx.y);
            }
            ls0 += __shfl_xor_sync(0xffffffffu, ls0, 1);
            ls0 += __shfl_xor_sync(0xffffffffu, ls0, 2);
            ls1 += __shfl_xor_sync(0xffffffffu, ls1, 1);
            ls1 += __shfl_xor_sync(0xffffffffu, ls1, 2);
            l0 += ls0;  l1 += ls1;

            #pragma unroll
            for (int ks = 0; ks < 4; ks++) {
                uint32_t af[4] = {ph0[2 * ks], ph1[2 * ks],
                                  ph0[2 * ks + 1], ph1[2 * ks + 1]};
                #pragma unroll
                for (int dp = 0; dp < 8; dp++) {
                    uint32_t bv[4];
                    uint32_t bo = aoffBT + (uint32_t)(ks * 16 * ROWE) * 2 + dp * 32;
                    ldsm4t(bv, bVH + bo);
                    mma16816(&o[(2 * dp) * 4],     af, bv);
                    mma16816(&o[(2 * dp + 1) * 4], af, bv + 2);
                }
            }
        }
    }

    // ================= epilogue =================
    const float hm = __ldg(&HM[h]);
    const float sc0 = hm / l0, sc1 = hm / l1;
    const int gr0 = q0 + wrow + (lane >> 2);
    float* O0 = O + ((size_t)bh * Sc + gr0) * Dc;
    float* O1 = O0 + 8 * Dc;
    #pragma unroll
    for (int t = 0; t < 16; t++) {
        int c0 = t * 8 + (lane & 3) * 2;
        *(float2*)&O0[c0] = make_float2(o[t * 4 + 0] * sc0, o[t * 4 + 1] * sc0);
        *(float2*)&O1[c0] = make_float2(o[t * 4 + 2] * sc1, o[t * 4 + 3] * sc1);
    }
}

extern "C" void kernel_launch(void* const* d_in, const int* in_sizes, int n_in,
                              void* d_out, int out_size)
{
    const float* q   = (const float*)d_in[0];
    const float* k   = (const float*)d_in[1];
    const float* v   = (const float*)d_in[2];
    const float* am  = (const float*)d_in[3];
    const float* hm  = (const float*)d_in[4];
    const float* ctx = (const float*)d_in[5];
    float* out = (float*)d_out;

    convert_split<<<dim3(BHSD / (256 * 4), 2), 256>>>(k, v);

    cudaFuncSetAttribute(attn_hmma, cudaFuncAttributeMaxDynamicSharedMemorySize,
                         SMEM_BYTES);
    attn_hmma<<<512, NTH, SMEM_BYTES>>>(q, am, hm, ctx, out);
}